// round 9
// baseline (speedup 1.0000x reference)
#include <cuda_runtime.h>

#define WL_L      2048
#define WL_LMASK  2047
#define WL_D      32
#define WL_B      16
#define WL_NT     128                 // 4 warps, one per d-plane

#define WL_G      4                   // d-planes per CTA
#define WL_T      256                 // outputs per plane per CTA
#define WL_HALO   112                 // x halo (28 quads), >= 105 back-reach
#define WL_EXT    (WL_T + WL_HALO)    // 368 floats = 92 quads
#define WL_NCHUNK (WL_L / WL_T)       // 8
#define WL_NDG    (WL_D / WL_G)       // 8

__global__ __launch_bounds__(WL_NT) void wavelet_db4_kernel(
    const float* __restrict__ x,       // (B, L, D)
    const float* __restrict__ w_dec,   // (4, L, L) — only 8 taps read
    const float* __restrict__ v_dec,   // (4, L, L) — only 8 taps read
    float* __restrict__ out)           // (B, D, L, 5)
{
    __shared__ __align__(16) float xs [WL_G][WL_EXT];
    __shared__ __align__(16) float v1s[WL_G][WL_EXT];
    __shared__ float gs[8];
    __shared__ float hs[8];
    __shared__ float2 cs[22];          // (cg2[t], ch2[t]) composites

    const int tid   = threadIdx.x;
    const int blk   = blockIdx.x;
    const int chunk = blk & (WL_NCHUNK - 1);
    const int dg    = (blk >> 3) & (WL_NDG - 1);
    const int b     = blk >> 6;
    const int M0    = chunk * WL_T;
    const int base  = M0 - WL_HALO;

    const int p    = tid >> 5;        // plane 0..3 == warp id
    const int lane = tid & 31;
    const int hq   = lane - 4;        // halo quad id; valid hq in [7,27] (lanes 11..31)

    // ── warp 0: base taps + composite taps (while other warps gather)
    if (p == 0) {
        if (lane < 8) {
            int col = (WL_L - lane) & WL_LMASK;   // f[0][0][(0-i) mod L] = tap[i]
            gs[lane] = v_dec[col];
            hs[lane] = w_dec[col];
        }
        __syncwarp();
        if (lane < 22) {
            // cg2[t] = sum_k g[k]*g[t-2k];  ch2[t] = sum_k h[k]*g[t-2k]
            float cg = 0.f, ch = 0.f;
            #pragma unroll
            for (int k = 0; k < 8; k++) {
                int i = lane - 2 * k;
                if (i >= 0 && i < 8) {
                    cg += gs[k] * gs[i];
                    ch += hs[k] * gs[i];
                }
            }
            cs[lane] = make_float2(cg, ch);
        }
    }

    // ── amortized gather: one float4 across 4 adjacent d per x-row
    {
        const float* xp = x + ((size_t)b * WL_L * WL_D) + dg * WL_G;
        #pragma unroll
        for (int l = tid; l < WL_EXT; l += WL_NT) {
            int gl = (base + l) & WL_LMASK;
            float4 qv = *(const float4*)(xp + (size_t)gl * WL_D);
            xs[0][l] = qv.x; xs[1][l] = qv.y; xs[2][l] = qv.z; xs[3][l] = qv.w;
        }
    }
    __syncthreads();   // the ONLY CTA-wide barrier

    float h[8];
    #pragma unroll
    for (int i = 0; i < 8; i++) h[i] = hs[i];

    const float4* xs4 = (const float4*)(&xs [p][0]);
    const float4* v1r = (const float4*)(&v1s[p][0]);
    float4*       v1w = (float4*)(&v1s[p][0]);

    // two output quads per thread: quad indices 28+lane and 60+lane
    int b4s[2]; b4s[0] = 28 + lane; b4s[1] = 60 + lane;

    float w0[2][4], w1[2][4];

    // ── stage A: x → v1 (cg2, 22 taps), w1 (ch2, 22 taps), w0 (h, 8 taps)
    #pragma unroll
    for (int s = 0; s < 2; s++) {
        const int b4 = b4s[s];
        float win[28];
        #pragma unroll
        for (int kk = 0; kk < 7; kk++) {
            float4 qv = xs4[b4 - 6 + kk];
            win[4*kk+0] = qv.x; win[4*kk+1] = qv.y;
            win[4*kk+2] = qv.z; win[4*kk+3] = qv.w;
        }
        float v1a[4] = {0.f, 0.f, 0.f, 0.f};
        #pragma unroll
        for (int j = 0; j < 4; j++) w1[s][j] = 0.f;
        #pragma unroll
        for (int t = 0; t < 22; t++) {
            float2 c = cs[t];
            #pragma unroll
            for (int j = 0; j < 4; j++) {
                v1a[j]   += c.x * win[24 + j - t];
                w1[s][j] += c.y * win[24 + j - t];
            }
        }
        #pragma unroll
        for (int j = 0; j < 4; j++) w0[s][j] = 0.f;
        #pragma unroll
        for (int i = 0; i < 8; i++) {
            #pragma unroll
            for (int j = 0; j < 4; j++)
                w0[s][j] += h[i] * win[24 + j - i];
        }
        v1w[b4] = make_float4(v1a[0], v1a[1], v1a[2], v1a[3]);
    }
    // halo v1 (quads 7..27), composite cg2 only
    if (hq >= 7) {
        float win[28];
        #pragma unroll
        for (int kk = 0; kk < 7; kk++) {
            float4 qv = xs4[hq - 6 + kk];
            win[4*kk+0] = qv.x; win[4*kk+1] = qv.y;
            win[4*kk+2] = qv.z; win[4*kk+3] = qv.w;
        }
        float a[4] = {0.f, 0.f, 0.f, 0.f};
        #pragma unroll
        for (int t = 0; t < 22; t++) {
            float cg = cs[t].x;
            #pragma unroll
            for (int j = 0; j < 4; j++)
                a[j] += cg * win[24 + j - t];
        }
        v1w[hq] = make_float4(a[0], a[1], a[2], a[3]);
    }
    __syncwarp();      // the ONLY inter-stage barrier (warp-private plane)

    // ── stage B: v1 → w2 (h, 8 taps @4), w3 (ch2, 22 taps @4), v3 (cg2, 22 taps @4)
    const int bd = b * WL_D + dg * WL_G + p;
    #pragma unroll
    for (int s = 0; s < 2; s++) {
        const int b4 = b4s[s];
        float w2[4] = {0,0,0,0}, w3[4] = {0,0,0,0}, v3[4] = {0,0,0,0};
        #pragma unroll
        for (int t = 0; t < 22; t++) {
            float4 qv = v1r[b4 - t];
            float2 c  = cs[t];
            v3[0] += c.x * qv.x; v3[1] += c.x * qv.y;
            v3[2] += c.x * qv.z; v3[3] += c.x * qv.w;
            w3[0] += c.y * qv.x; w3[1] += c.y * qv.y;
            w3[2] += c.y * qv.z; w3[3] += c.y * qv.w;
            if (t < 8) {
                w2[0] += h[t] * qv.x; w2[1] += h[t] * qv.y;
                w2[2] += h[t] * qv.z; w2[3] += h[t] * qv.w;
            }
        }

        float o[20];
        #pragma unroll
        for (int j = 0; j < 4; j++) {
            o[j*5 + 0] = w0[s][j];
            o[j*5 + 1] = w1[s][j];
            o[j*5 + 2] = w2[j];
            o[j*5 + 3] = w3[j];
            o[j*5 + 4] = v3[j];
        }
        const int m0 = M0 + 4 * (b4 - 28);
        float4* og = (float4*)(out + ((size_t)bd * WL_L + m0) * 5);
        #pragma unroll
        for (int kk = 0; kk < 5; kk++) og[kk] = ((const float4*)o)[kk];
    }
}

extern "C" void kernel_launch(void* const* d_in, const int* in_sizes, int n_in,
                              void* d_out, int out_size) {
    const float* x     = (const float*)d_in[0];
    const float* w_dec = (const float*)d_in[1];
    const float* v_dec = (const float*)d_in[2];
    float* out = (float*)d_out;

    wavelet_db4_kernel<<<WL_B * WL_NDG * WL_NCHUNK, WL_NT>>>(x, w_dec, v_dec, out);
}